// round 2
// baseline (speedup 1.0000x reference)
#include <cuda_runtime.h>
#include <cstdint>
#include <cstdio>

#define DM   768
#define DI   1536
#define DS   64
#define DTR  48
#define SEQL 2048
#define NB   4            /* effective batch: 2 orig x 2 channel-flip */
#define MTOK (NB*SEQL)    /* 8192 token rows */
#define XPW  176          /* DTR + 2*DS */

/* ---------------- scratch (static device globals; no allocation) -------- */
__device__ float g_act1[2*DM*SEQL];
__device__ float g_hdw [2*DM*SEQL];
__device__ float g_h2  [2*SEQL*DM];
__device__ float g_X2  [MTOK*DM];
__device__ float g_xz  [MTOK*2*DI];
__device__ float g_xmf [NB*DI*SEQL];
__device__ float g_xmb [NB*DI*SEQL];
__device__ float g_xpf [MTOK*XPW];
__device__ float g_xpb [MTOK*XPW];
__device__ float g_dttmf[MTOK*DI];
__device__ float g_dttmb[MTOK*DI];
__device__ float g_dtf [NB*DI*SEQL];
__device__ float g_dtb [NB*DI*SEQL];
__device__ float g_yf  [NB*DI*SEQL];
__device__ float g_yb  [NB*DI*SEQL];
__device__ float g_u   [MTOK*DI];
__device__ float g_v   [MTOK*DM];

/* ---------------- 1. BatchNorm3d(eval) + LeakyReLU ---------------------- */
__global__ void bn_lrelu_k(const float* __restrict__ x, const float* __restrict__ g,
                           const float* __restrict__ be, const float* __restrict__ mu,
                           const float* __restrict__ var) {
    int i = blockIdx.x * 256 + threadIdx.x;
    if (i >= 2*DM*SEQL) return;
    int c = (i / SEQL) % DM;
    float v = (x[i] - mu[c]) * rsqrtf(var[c] + 1e-5f) * g[c] + be[c];
    g_act1[i] = v > 0.f ? v : 0.01f * v;
}

/* ---------------- 2. depthwise conv3d 3x3x3 SAME ------------------------ */
__global__ void dwconv_k(const float* __restrict__ wt) {
    int i = blockIdx.x * 256 + threadIdx.x;
    if (i >= 2*DM*SEQL) return;
    int w = i & 15, h = (i >> 4) & 15, d = (i >> 8) & 7;
    int c = (i >> 11) % DM;
    int b = i / (DM * SEQL);
    const float* wp = wt + c * 27;
    const float* ip = g_act1 + (size_t)(b*DM + c) * SEQL;
    float acc = 0.f;
    #pragma unroll
    for (int kd = 0; kd < 3; kd++) {
        int dd = d + kd - 1; if (dd < 0 || dd > 7) continue;
        #pragma unroll
        for (int kh = 0; kh < 3; kh++) {
            int hh = h + kh - 1; if (hh < 0 || hh > 15) continue;
            #pragma unroll
            for (int kw = 0; kw < 3; kw++) {
                int ww = w + kw - 1; if (ww < 0 || ww > 15) continue;
                acc += wp[kd*9 + kh*3 + kw] * ip[dd*256 + hh*16 + ww];
            }
        }
    }
    g_hdw[i] = acc;
}

/* ---------------- generic fp32 GEMM:  C[m,n] = sum_k A[m,k]*W[n,k] ------ */
/* A: row-major [M,K] (TRANSA=0, lda=row stride) or [K,M] (TRANSA=1, lda=k-row stride)
   W: row-major [N,K].  EPI: 0 none, 1 leaky-relu, 2 softplus(x+bias[n]).  */
#define BM 128
#define BN 128
#define BKK 16
template<int EPI, int TRANSA>
__global__ __launch_bounds__(256) void sgemm_k(
    const float* __restrict__ A, const float* __restrict__ W,
    float* __restrict__ C, const float* __restrict__ bias,
    int Mb, int N, int K, int lda, long aBS, long cBS)
{
    __shared__ float As[BKK][BM + 4];
    __shared__ float Bs[BKK][BN + 4];
    const float* Ab = A + (long)blockIdx.z * aBS;
    float* Cb = C + (long)blockIdx.z * cBS;
    int n0 = blockIdx.x * BN, m0 = blockIdx.y * BM;
    int tid = threadIdx.x;
    int tx = tid & 15, ty = tid >> 4;
    float acc[8][8];
    #pragma unroll
    for (int i = 0; i < 8; i++)
        #pragma unroll
        for (int j = 0; j < 8; j++) acc[i][j] = 0.f;

    for (int k0 = 0; k0 < K; k0 += BKK) {
        if (TRANSA) {
            #pragma unroll
            for (int r = 0; r < 2; r++) {
                int e = tid + r * 256;
                int kr = e >> 5, m4 = e & 31;
                float4 v = *(const float4*)&Ab[(long)(k0 + kr) * lda + m0 + m4*4];
                *(float4*)&As[kr][m4*4] = v;
            }
        } else {
            #pragma unroll
            for (int r = 0; r < 2; r++) {
                int e = tid + r * 256;
                int mr = e >> 2, kc = (e & 3) * 4;
                float4 v = *(const float4*)&Ab[(long)(m0 + mr) * lda + k0 + kc];
                As[kc+0][mr] = v.x; As[kc+1][mr] = v.y;
                As[kc+2][mr] = v.z; As[kc+3][mr] = v.w;
            }
        }
        #pragma unroll
        for (int r = 0; r < 2; r++) {
            int e = tid + r * 256;
            int nr = e >> 2, kc = (e & 3) * 4;
            float4 v = make_float4(0.f, 0.f, 0.f, 0.f);
            if (n0 + nr < N) v = *(const float4*)&W[(long)(n0 + nr) * K + k0 + kc];
            Bs[kc+0][nr] = v.x; Bs[kc+1][nr] = v.y;
            Bs[kc+2][nr] = v.z; Bs[kc+3][nr] = v.w;
        }
        __syncthreads();
        #pragma unroll
        for (int k = 0; k < BKK; k++) {
            float a[8], bb[8];
            *(float4*)&a[0]  = *(const float4*)&As[k][ty*8];
            *(float4*)&a[4]  = *(const float4*)&As[k][ty*8 + 4];
            *(float4*)&bb[0] = *(const float4*)&Bs[k][tx*8];
            *(float4*)&bb[4] = *(const float4*)&Bs[k][tx*8 + 4];
            #pragma unroll
            for (int i = 0; i < 8; i++)
                #pragma unroll
                for (int j = 0; j < 8; j++) acc[i][j] += a[i] * bb[j];
        }
        __syncthreads();
    }
    #pragma unroll
    for (int i = 0; i < 8; i++) {
        int m = m0 + ty*8 + i;
        #pragma unroll
        for (int j = 0; j < 8; j++) {
            int n = n0 + tx*8 + j;
            if (n < N) {
                float v = acc[i][j];
                if (EPI == 1) v = v > 0.f ? v : 0.01f * v;
                else if (EPI == 2) {
                    v += bias[n];
                    v = (v > 20.f) ? v : log1pf(__expf(v));
                }
                Cb[(long)m * N + n] = v;
            }
        }
    }
}

/* ---------------- 4. LayerNorm over channels; emit X2 (orig + c-flip) --- */
__global__ void ln_k(const float* __restrict__ gam, const float* __restrict__ bet) {
    int m = blockIdx.x;                 /* token 0..4095 */
    __shared__ float red[16];
    const float* row = g_h2 + (size_t)m * DM;
    float s = 0.f, s2 = 0.f;
    for (int c = threadIdx.x; c < DM; c += 256) { float v = row[c]; s += v; s2 += v*v; }
    #pragma unroll
    for (int o = 16; o; o >>= 1) {
        s  += __shfl_xor_sync(~0u, s, o);
        s2 += __shfl_xor_sync(~0u, s2, o);
    }
    int wid = threadIdx.x >> 5, ln = threadIdx.x & 31;
    if (ln == 0) { red[wid] = s; red[8 + wid] = s2; }
    __syncthreads();
    float ts = 0.f, ts2 = 0.f;
    #pragma unroll
    for (int i = 0; i < 8; i++) { ts += red[i]; ts2 += red[8 + i]; }
    float mu = ts / 768.f;
    float var = ts2 / 768.f - mu * mu;
    float rs = rsqrtf(var + 1e-5f);
    for (int c = threadIdx.x; c < DM; c += 256) {
        float v = (row[c] - mu) * rs * gam[c] + bet[c];
        g_X2[(size_t)m * DM + c] = v;
        g_X2[(size_t)(4096 + m) * DM + (DM - 1 - c)] = v;
    }
}

/* ---------------- 6. causal + anti-causal depthwise conv1d + SiLU ------- */
/* reads g_xz (token-major), writes xm_f / xm_b in [b, d, t] layout        */
__global__ __launch_bounds__(256) void conv1d_k(const float* __restrict__ cw,
                                                const float* __restrict__ cb) {
    __shared__ float s[32][71];
    __shared__ float sw[32][4];
    __shared__ float sb[32];
    int b = blockIdx.z, d0 = blockIdx.y * 32, t0 = blockIdx.x * 64;
    int tid = threadIdx.x;
    if (tid < 128) sw[tid >> 2][tid & 3] = cw[(d0 + (tid >> 2)) * 4 + (tid & 3)];
    if (tid < 32)  sb[tid] = cb[d0 + tid];
    for (int e = tid; e < 32 * 70; e += 256) {
        int dd = e & 31, tt = e >> 5;
        int t = t0 - 3 + tt;
        float v = 0.f;
        if (t >= 0 && t < SEQL) v = g_xz[((size_t)(b * SEQL + t)) * (2*DI) + d0 + dd];
        s[dd][tt] = v;
    }
    __syncthreads();
    int tt = tid & 63, dg = tid >> 6;
    for (int dl = dg; dl < 32; dl += 4) {
        float w0 = sw[dl][0], w1 = sw[dl][1], w2 = sw[dl][2], w3 = sw[dl][3], bb = sb[dl];
        /* fwd: sum_j w[j]*x[t-3+j]   bwd: sum_j w[j]*x[t+3-j] */
        float f = w0*s[dl][tt]   + w1*s[dl][tt+1] + w2*s[dl][tt+2] + w3*s[dl][tt+3] + bb;
        float g = w0*s[dl][tt+6] + w1*s[dl][tt+5] + w2*s[dl][tt+4] + w3*s[dl][tt+3] + bb;
        size_t o = ((size_t)(b * DI + d0 + dl)) * SEQL + t0 + tt;
        g_xmf[o] = f / (1.f + __expf(-f));
        g_xmb[o] = g / (1.f + __expf(-g));
    }
}

/* ---------------- 9. [b,t,d] -> [b,d,t] transpose ----------------------- */
__global__ void transpose_k(const float* __restrict__ in, float* __restrict__ out) {
    __shared__ float s[32][33];
    int b = blockIdx.z, d0 = blockIdx.y * 32, t0 = blockIdx.x * 32;
    int tx = threadIdx.x, ty = threadIdx.y;     /* 32 x 8 */
    #pragma unroll
    for (int i = 0; i < 4; i++) {
        int t = t0 + ty + i*8;
        s[ty + i*8][tx] = in[((size_t)(b * SEQL + t)) * DI + d0 + tx];
    }
    __syncthreads();
    #pragma unroll
    for (int i = 0; i < 4; i++) {
        int d = d0 + ty + i*8;
        out[((size_t)(b * DI + d)) * SEQL + t0 + tx] = s[tx][ty + i*8];
    }
}

/* ---------------- 10. selective scan (fwd + bwd) ------------------------ */
__global__ __launch_bounds__(256) void scan_k(const float* __restrict__ A_log) {
    __shared__ float4 shbc[32][32];
    int dir = blockIdx.z, b = blockIdx.y;
    int wid = threadIdx.x >> 5, lane = threadIdx.x & 31;
    int d = blockIdx.x * 8 + wid;
    const float* dt = (dir ? g_dtb : g_dtf) + ((size_t)(b*DI + d)) * SEQL;
    const float* xm = (dir ? g_xmb : g_xmf) + ((size_t)(b*DI + d)) * SEQL;
    const float* xp = (dir ? g_xpb : g_xpf) + (size_t)b * SEQL * XPW;
    float* y = (dir ? g_yb : g_yf) + ((size_t)(b*DI + d)) * SEQL;
    const float L2E = 1.4426950408889634f;
    float A1 = -__expf(A_log[d*DS + lane])       * L2E;
    float A2 = -__expf(A_log[d*DS + 32 + lane])  * L2E;
    float h1 = 0.f, h2 = 0.f;
    for (int s0 = 0; s0 < SEQL; s0 += 32) {
        __syncthreads();
        for (int e = threadIdx.x; e < 1024; e += 256) {
            int r = e >> 5, n = e & 31;
            int t = dir ? (SEQL - 1 - (s0 + r)) : (s0 + r);
            const float* p = xp + (size_t)t * XPW;
            shbc[r][n] = make_float4(p[48 + n], p[80 + n], p[112 + n], p[144 + n]);
        }
        int tl = dir ? (SEQL - 1 - (s0 + lane)) : (s0 + lane);
        float dtv_b = dt[tl];
        float xv_b  = xm[tl];
        __syncthreads();
        float ykeep = 0.f;
        #pragma unroll 8
        for (int j = 0; j < 32; j++) {
            float dtv = __shfl_sync(~0u, dtv_b, j);
            float xv  = __shfl_sync(~0u, xv_b, j);
            float4 bc = shbc[j][lane];
            float e1, e2;
            asm("ex2.approx.f32 %0, %1;" : "=f"(e1) : "f"(dtv * A1));
            asm("ex2.approx.f32 %0, %1;" : "=f"(e2) : "f"(dtv * A2));
            float uu = dtv * xv;
            h1 = e1 * h1 + uu * bc.x;
            h2 = e2 * h2 + uu * bc.y;
            float p = h1 * bc.z + h2 * bc.w;
            #pragma unroll
            for (int o = 16; o; o >>= 1) p += __shfl_xor_sync(~0u, p, o);
            if (j == lane) ykeep = p;
        }
        y[dir ? (SEQL - 1 - s0 - lane) : (s0 + lane)] = ykeep;
    }
}

/* ---------------- 11. combine dirs + gate, transpose to token-major ----- */
__global__ void combine_k(const float* __restrict__ Dskip) {
    __shared__ float s[32][33];
    int b = blockIdx.z, d0 = blockIdx.y * 32, t0 = blockIdx.x * 32;
    int tx = threadIdx.x, ty = threadIdx.y;     /* 32 x 8 */
    #pragma unroll
    for (int i = 0; i < 4; i++) {
        int d = d0 + ty + i*8;
        size_t I = ((size_t)(b * DI + d)) * SEQL + t0 + tx;
        float v = g_yf[I] + g_yb[I] + Dskip[d] * (g_xmf[I] + g_xmb[I]);
        s[ty + i*8][tx] = v;
    }
    __syncthreads();
    #pragma unroll
    for (int i = 0; i < 4; i++) {
        int t = t0 + ty + i*8;
        int d = d0 + tx;
        float z = g_xz[((size_t)(b * SEQL + t)) * (2*DI) + DI + d];
        float sz = z / (1.f + __expf(-z));
        g_u[((size_t)(b * SEQL + t)) * DI + d] = s[tx][ty + i*8] * sz;
    }
}

/* ---------------- 13. final: average 4 directions ----------------------- */
__global__ void final_k(float* __restrict__ out) {
    int i = blockIdx.x * 256 + threadIdx.x;
    if (i >= 2 * SEQL * DM) return;
    int c = i % DM;
    size_t ml = (size_t)(i / DM);             /* b*L + l, b in 0..1 */
    out[i] = 0.25f * (g_v[ml * DM + c] +
                      g_v[(ml + (size_t)2 * SEQL) * DM + (DM - 1 - c)]);
}

/* ------------------------------------------------------------------------ */
extern "C" void kernel_launch(void* const* d_in, const int* in_sizes, int n_in,
                              void* d_out, int out_size) {
    const float* x        = (const float*)d_in[0];
    const float* bn_gamma = (const float*)d_in[1];
    const float* bn_beta  = (const float*)d_in[2];
    const float* bn_mean  = (const float*)d_in[3];
    const float* bn_var   = (const float*)d_in[4];
    const float* dw_w     = (const float*)d_in[5];
    const float* pw_w     = (const float*)d_in[6];
    const float* ln_gamma = (const float*)d_in[7];
    const float* ln_beta  = (const float*)d_in[8];
    const float* W_in     = (const float*)d_in[9];
    const float* conv_w   = (const float*)d_in[10];
    const float* conv_b   = (const float*)d_in[11];
    const float* W_x      = (const float*)d_in[12];
    const float* W_dt     = (const float*)d_in[13];
    const float* b_dt     = (const float*)d_in[14];
    const float* A_log    = (const float*)d_in[15];
    const float* D_skip   = (const float*)d_in[16];
    const float* W_out    = (const float*)d_in[17];
    float* out            = (float*)d_out;

    float *p_hdw, *p_h2, *p_X2, *p_xz, *p_xmf, *p_xmb, *p_xpf, *p_xpb,
          *p_dttmf, *p_dttmb, *p_dtf, *p_dtb, *p_u, *p_v;
    cudaGetSymbolAddress((void**)&p_hdw,  g_hdw);
    cudaGetSymbolAddress((void**)&p_h2,   g_h2);
    cudaGetSymbolAddress((void**)&p_X2,   g_X2);
    cudaGetSymbolAddress((void**)&p_xz,   g_xz);
    cudaGetSymbolAddress((void**)&p_xmf,  g_xmf);
    cudaGetSymbolAddress((void**)&p_xmb,  g_xmb);
    cudaGetSymbolAddress((void**)&p_xpf,  g_xpf);
    cudaGetSymbolAddress((void**)&p_xpb,  g_xpb);
    cudaGetSymbolAddress((void**)&p_dttmf, g_dttmf);
    cudaGetSymbolAddress((void**)&p_dttmb, g_dttmb);
    cudaGetSymbolAddress((void**)&p_dtf,  g_dtf);
    cudaGetSymbolAddress((void**)&p_dtb,  g_dtb);
    cudaGetSymbolAddress((void**)&p_u,    g_u);
    cudaGetSymbolAddress((void**)&p_v,    g_v);

    /* front-end */
    bn_lrelu_k<<<(2*DM*SEQL + 255)/256, 256>>>(x, bn_gamma, bn_beta, bn_mean, bn_var);
    dwconv_k<<<(2*DM*SEQL + 255)/256, 256>>>(dw_w);
    /* pointwise conv as GEMM (A^T = g_hdw channel-major), LeakyReLU epilogue */
    sgemm_k<1,1><<<dim3(6,16,2), 256>>>(p_hdw, pw_w, p_h2, nullptr,
                                        SEQL, DM, DM, SEQL,
                                        (long)DM*SEQL, (long)SEQL*DM);
    /* layernorm -> X2 (orig + channel-flipped rows) */
    ln_k<<<2*SEQL, 256>>>(ln_gamma, ln_beta);
    /* in_proj: [8192,768] x [3072,768]^T -> xz */
    sgemm_k<0,0><<<dim3(24,64,1), 256>>>(p_X2, W_in, p_xz, nullptr,
                                         MTOK, 2*DI, DM, DM, 0, 0);
    /* dual-direction depthwise conv1d + SiLU -> xm_f / xm_b  [b,d,t] */
    conv1d_k<<<dim3(32,48,NB), 256>>>(conv_w, conv_b);
    /* x_proj (A^T layout), per direction */
    sgemm_k<0,1><<<dim3(2,16,NB), 256>>>(p_xmf, W_x, p_xpf, nullptr,
                                         SEQL, XPW, DI, SEQL,
                                         (long)DI*SEQL, (long)SEQL*XPW);
    sgemm_k<0,1><<<dim3(2,16,NB), 256>>>(p_xmb, W_x, p_xpb, nullptr,
                                         SEQL, XPW, DI, SEQL,
                                         (long)DI*SEQL, (long)SEQL*XPW);
    /* dt projection + softplus (token-major), then transpose to [b,d,t] */
    sgemm_k<2,0><<<dim3(12,64,1), 256>>>(p_xpf, W_dt, p_dttmf, b_dt,
                                         MTOK, DI, DTR, XPW, 0, 0);
    sgemm_k<2,0><<<dim3(12,64,1), 256>>>(p_xpb, W_dt, p_dttmb, b_dt,
                                         MTOK, DI, DTR, XPW, 0, 0);
    transpose_k<<<dim3(64,48,NB), dim3(32,8)>>>(p_dttmf, p_dtf);
    transpose_k<<<dim3(64,48,NB), dim3(32,8)>>>(p_dttmb, p_dtb);
    /* selective scan, both directions */
    scan_k<<<dim3(DI/8, NB, 2), 256>>>(A_log);
    /* combine + gate -> u (token-major) */
    combine_k<<<dim3(64,48,NB), dim3(32,8)>>>(D_skip);
    /* out_proj */
    sgemm_k<0,0><<<dim3(6,64,1), 256>>>(p_u, W_out, p_v, nullptr,
                                        MTOK, DM, DI, DI, 0, 0);
    /* average the 4 directions */
    final_k<<<(2*SEQL*DM + 255)/256, 256>>>(out);
    (void)in_sizes; (void)n_in; (void)out_size;
}